// round 1
// baseline (speedup 1.0000x reference)
#include <cuda_runtime.h>
#include <math.h>

// ---------------- constants ----------------
#define NRBF 32
__device__ __forceinline__ float ldg(const float* p) { return __ldg(p); }

// step = R_CUT/(N_RBF-1) = 5/31 ; width = R_CUT/N_RBF = 5/32
#define STEP      (0.16129032258064516f)   // 5/31
#define INV_STEP  (6.2f)                   // 31/5
#define INV_W     (6.4f)                   // 32/5
#define S_RATIO   (1.03225806451612903f)   // step/width = 32/31
#define HALF_S2   (0.53277835587929240f)   // 0.5*(32/31)^2
#define G_CONST   (0.34453600290f)         // exp(-(32/31)^2), high-precision
#define R_CUTF    (5.0f)

#define C1  (0.48860251190291992f)
#define C2A (1.09254843059207907f)
#define C2B (0.31539156525252005f)
#define C2C (0.54627421529603953f)

__global__ void __launch_bounds__(256)
geo_kernel(const float* __restrict__ R,
           const float* __restrict__ pair_mask,
           const float* __restrict__ point_mask,
           const int*   __restrict__ idx_i,
           const int*   __restrict__ idx_j,
           float* __restrict__ rbf_out,
           float* __restrict__ chi_out,
           int n_pairs)
{
    __shared__ float srbf[256 * 33];   // padded rows: conflict-free

    const int tid  = threadIdx.x;
    const int lane = tid & 31;
    const long long p = (long long)blockIdx.x * 256 + tid;
    const bool valid = (p < (long long)n_pairs);

    int i = 0, j = 0;
    float pm = 0.f;
    if (valid) {
        i  = __ldg(idx_i + p);
        j  = __ldg(idx_j + p);
        pm = __ldg(pair_mask + p);
    }

    float rx = 0.f, ry = 0.f, rz = 0.f;
    if (valid) {
        rx = (ldg(R + 3*(size_t)j    ) - ldg(R + 3*(size_t)i    )) * pm;
        ry = (ldg(R + 3*(size_t)j + 1) - ldg(R + 3*(size_t)i + 1)) * pm;
        rz = (ldg(R + 3*(size_t)j + 2) - ldg(R + 3*(size_t)i + 2)) * pm;
    }

    const float sq  = fmaf(rx, rx, fmaf(ry, ry, rz * rz));
    const float inv = (sq > 0.f) ? rsqrtf(sq) : 0.f;   // 1/sqrt(sq)
    const float d   = sq * inv * pm;                    // sqrt(sq)*pm (0 if sq==0)

    // ---------- RBF via Gaussian ladder (2 exps + Newton rcp) ----------
    // k0 = nearest center index; rbf[k] = exp(-0.5*((d - k*STEP)/W)^2)
    float kk = fminf((float)__float2int_rn(d * INV_STEP), 31.0f);
    const int   k0    = (int)kk;
    const float delta = d - kk * STEP;
    const float t0    = delta * INV_W;

    const float A  = __expf(-0.5f * t0 * t0);
    const float qu = __expf(fmaf(t0, S_RATIO, -HALF_S2));
    // qd = G_CONST / qu  via bit-trick reciprocal + 3 Newton steps (FMA pipe only)
    float rq = __uint_as_float(0x7EF311C3u - __float_as_uint(qu));
    rq = rq * (2.0f - qu * rq);
    rq = rq * (2.0f - qu * rq);
    rq = rq * (2.0f - qu * rq);
    const float qd = G_CONST * rq;

    float* row = &srbf[tid * 33];
    row[k0] = A * pm;
    {   // downward chain: r_{k-1} = r_k * q,  q *= G
        float r = A, q = qd;
        for (int k = k0 - 1; k >= 0; --k) { r *= q; q *= G_CONST; row[k] = r * pm; }
    }
    {   // upward chain
        float r = A, q = qu;
        for (int k = k0 + 1; k < NRBF; ++k) { r *= q; q *= G_CONST; row[k] = r * pm; }
    }

    // ---------- phi (cutoff) : cos(pi*x) = -sin(pi*(x-1/2)), Taylor in h^2 ----------
    const float x = d * 0.2f;
    const float h = x - 0.5f;
    const float v = h * h;
    float sp = fmaf(v, fmaf(v, fmaf(v, fmaf(v, 0.0821458866f, -0.599264529f),
                                    2.55016404f), -5.16771278f), 3.14159265f);
    const float cospix = -h * sp;
    const float phi = (d < R_CUTF) ? 0.5f * (cospix + 1.0f) * pm : 0.f;

    // ---------- spherical harmonics l1,l2 ----------
    const float um = (d != 0.f) ? inv : 0.f;
    const float ux = rx * um * pm;
    const float uy = ry * um * pm;
    const float uz = rz * um * pm;

    const float pmi   = valid ? __ldg(point_mask + i) : 0.f;
    const float scale = phi * pm * pmi;   // sph carries *pm, weighted = sph*phi, chi *= point_mask

    float vv[8];
    vv[0] = C1 * uy * scale;
    vv[1] = C1 * uz * scale;
    vv[2] = C1 * ux * scale;
    vv[3] = C2A * ux * uy * scale;
    vv[4] = C2A * uy * uz * scale;
    vv[5] = C2B * fmaf(3.f, uz * uz, -1.f) * scale;
    vv[6] = C2A * ux * uz * scale;
    vv[7] = C2C * (ux * ux - uy * uy) * scale;

    // ---------- warp segmented reduction on sorted idx_i, then leader atomics ----------
    int ii = valid ? i : 0x7fffffff;
    const unsigned full = 0xffffffffu;
    #pragma unroll
    for (int off = 1; off < 32; off <<= 1) {
        int i2 = __shfl_down_sync(full, ii, off);
        bool take = (lane + off < 32) && (i2 == ii);
        #pragma unroll
        for (int c = 0; c < 8; ++c) {
            float t = __shfl_down_sync(full, vv[c], off);
            if (take) vv[c] += t;
        }
    }
    int prev = __shfl_up_sync(full, ii, 1);
    bool leader = (lane == 0) || (prev != ii);
    if (leader && ii != 0x7fffffff) {
        float* dst = chi_out + (size_t)ii * 8;
        #pragma unroll
        for (int c = 0; c < 8; ++c) atomicAdd(dst + c, vv[c]);
    }

    // ---------- coalesced rbf writeback through smem ----------
    __syncthreads();
    const size_t base = (size_t)blockIdx.x * (256 * 32);
    long long rem64 = (long long)n_pairs * 32 - (long long)base;
    int limit = (rem64 >= 8192) ? 8192 : (rem64 > 0 ? (int)rem64 : 0);
    #pragma unroll
    for (int it = 0; it < 32; ++it) {
        int lin = it * 256 + tid;
        if (lin < limit) {
            int pp = lin >> 5, k = lin & 31;
            rbf_out[base + lin] = srbf[pp * 33 + k];
        }
    }
}

extern "C" void kernel_launch(void* const* d_in, const int* in_sizes, int n_in,
                              void* d_out, int out_size)
{
    const float* R          = (const float*)d_in[0];
    const float* pair_mask  = (const float*)d_in[1];
    const float* point_mask = (const float*)d_in[2];
    const int*   idx_i      = (const int*)d_in[3];
    const int*   idx_j      = (const int*)d_in[4];
    // d_in[5] = z : unused by reference outputs

    const int n_pairs = in_sizes[1];   // pair_mask length
    const int n       = in_sizes[2];   // point_mask length

    float* rbf_out = (float*)d_out;
    float* chi_out = rbf_out + (size_t)n_pairs * NRBF;

    // zero the chi accumulation region (graph-capturable async memset)
    cudaMemsetAsync(chi_out, 0, (size_t)n * 8 * sizeof(float), 0);

    int blocks = (n_pairs + 255) / 256;
    geo_kernel<<<blocks, 256>>>(R, pair_mask, point_mask, idx_i, idx_j,
                                rbf_out, chi_out, n_pairs);
}

// round 2
// speedup vs baseline: 1.0511x; 1.0511x over previous
#include <cuda_runtime.h>
#include <math.h>

#define NRBF 32
#define RCAP 131072   // capacity for packed-R table (n = 100000 in this problem)

__device__ float4 g_R4[RCAP];

// step = R_CUT/(N_RBF-1) = 5/31 ; width = R_CUT/N_RBF = 5/32
#define STEP      (0.16129032258064516f)
#define INV_STEP  (6.2f)
#define INV_W     (6.4f)
#define S_RATIO   (1.03225806451612903f)   // step/width
#define HALF_S2   (0.53277835587929240f)   // 0.5*(step/width)^2
#define G_CONST   (0.34453600290f)         // exp(-(32/31)^2)
#define R_CUTF    (5.0f)

#define C1  (0.48860251190291992f)
#define C2A (1.09254843059207907f)
#define C2B (0.31539156525252005f)
#define C2C (0.54627421529603953f)

__global__ void __launch_bounds__(256)
pack_R_kernel(const float* __restrict__ R, int n)
{
    int i = blockIdx.x * 256 + threadIdx.x;
    if (i < n) {
        g_R4[i] = make_float4(R[3*(size_t)i], R[3*(size_t)i + 1],
                              R[3*(size_t)i + 2], 0.f);
    }
}

template <bool USE4>
__global__ void __launch_bounds__(256)
geo_kernel(const float* __restrict__ R,
           const float* __restrict__ pair_mask,
           const float* __restrict__ point_mask,
           const int*   __restrict__ idx_i,
           const int*   __restrict__ idx_j,
           float* __restrict__ rbf_out,
           float* __restrict__ chi_out,
           int n_pairs)
{
    __shared__ float srbf[256 * 33];   // stride-33: conflict-free scalar access

    const int tid  = threadIdx.x;
    const int lane = tid & 31;
    const long long p = (long long)blockIdx.x * 256 + tid;
    const bool valid = (p < (long long)n_pairs);

    int i = 0, j = 0;
    float pm = 0.f;
    if (valid) {
        i  = __ldg(idx_i + p);
        j  = __ldg(idx_j + p);
        pm = __ldg(pair_mask + p);
    }

    float rx = 0.f, ry = 0.f, rz = 0.f;
    if (valid) {
        if (USE4) {
            const float4 a = g_R4[j];
            const float4 b = g_R4[i];
            rx = (a.x - b.x) * pm;
            ry = (a.y - b.y) * pm;
            rz = (a.z - b.z) * pm;
        } else {
            rx = (__ldg(R + 3*(size_t)j    ) - __ldg(R + 3*(size_t)i    )) * pm;
            ry = (__ldg(R + 3*(size_t)j + 1) - __ldg(R + 3*(size_t)i + 1)) * pm;
            rz = (__ldg(R + 3*(size_t)j + 2) - __ldg(R + 3*(size_t)i + 2)) * pm;
        }
    }

    const float sq  = fmaf(rx, rx, fmaf(ry, ry, rz * rz));
    const float inv = (sq > 0.f) ? rsqrtf(sq) : 0.f;
    const float d   = sq * inv * pm;

    // ---------- RBF via Gaussian ladder (2 exps + Newton rcp) ----------
    float kk = fminf((float)__float2int_rn(d * INV_STEP), 31.0f);
    const int   k0    = (int)kk;
    const float delta = d - kk * STEP;
    const float t0    = delta * INV_W;

    const float A  = __expf(-0.5f * t0 * t0);
    const float qu = __expf(fmaf(t0, S_RATIO, -HALF_S2));
    float rq = __uint_as_float(0x7EF311C3u - __float_as_uint(qu));
    rq = rq * (2.0f - qu * rq);
    rq = rq * (2.0f - qu * rq);
    rq = rq * (2.0f - qu * rq);
    const float qd = G_CONST * rq;

    float* row = &srbf[tid * 33];
    row[k0] = A * pm;
    {   // downward chain
        float r = A, q = qd;
        for (int k = k0 - 1; k >= 0; --k) { r *= q; q *= G_CONST; row[k] = r * pm; }
    }
    {   // upward chain
        float r = A, q = qu;
        for (int k = k0 + 1; k < NRBF; ++k) { r *= q; q *= G_CONST; row[k] = r * pm; }
    }

    // ---------- phi (cutoff): cos(pi*x) = -sin(pi*(x-1/2)) odd poly ----------
    const float x = d * 0.2f;
    const float h = x - 0.5f;
    const float v = h * h;
    float sp = fmaf(v, fmaf(v, fmaf(v, fmaf(v, 0.0821458866f, -0.599264529f),
                                    2.55016404f), -5.16771278f), 3.14159265f);
    const float cospix = -h * sp;
    const float phi = (d < R_CUTF) ? 0.5f * (cospix + 1.0f) * pm : 0.f;

    // ---------- spherical harmonics l1,l2 ----------
    const float um = (d != 0.f) ? inv : 0.f;
    const float ux = rx * um * pm;
    const float uy = ry * um * pm;
    const float uz = rz * um * pm;

    const float pmi   = valid ? __ldg(point_mask + i) : 0.f;
    const float scale = phi * pm * pmi;

    float vv[8];
    vv[0] = C1 * uy * scale;
    vv[1] = C1 * uz * scale;
    vv[2] = C1 * ux * scale;
    vv[3] = C2A * ux * uy * scale;
    vv[4] = C2A * uy * uz * scale;
    vv[5] = C2B * fmaf(3.f, uz * uz, -1.f) * scale;
    vv[6] = C2A * ux * uz * scale;
    vv[7] = C2C * (ux * ux - uy * uy) * scale;

    // ---------- warp segmented reduction (idx_i sorted) + leader atomics ----------
    int ii = valid ? i : 0x7fffffff;
    const unsigned full = 0xffffffffu;
    #pragma unroll
    for (int off = 1; off < 32; off <<= 1) {
        int i2 = __shfl_down_sync(full, ii, off);
        bool take = (lane + off < 32) && (i2 == ii);
        #pragma unroll
        for (int c = 0; c < 8; ++c) {
            float t = __shfl_down_sync(full, vv[c], off);
            if (take) vv[c] += t;
        }
    }
    int prev = __shfl_up_sync(full, ii, 1);
    bool leader = (lane == 0) || (prev != ii);
    if (leader && ii != 0x7fffffff) {
        float* dst = chi_out + (size_t)ii * 8;
        #pragma unroll
        for (int c = 0; c < 8; ++c) atomicAdd(dst + c, vv[c]);
    }

    // ---------- coalesced vectorized rbf writeback ----------
    __syncthreads();
    const size_t base4 = (size_t)blockIdx.x * (256 * 8);      // float4 units
    long long rem4 = ((long long)n_pairs * 32) / 4 - (long long)base4;
    int limit4 = (rem4 >= 2048) ? 2048 : (rem4 > 0 ? (int)rem4 : 0);
    float4* out4 = (float4*)rbf_out;
    #pragma unroll
    for (int it = 0; it < 8; ++it) {
        int g = it * 256 + tid;                // chunk id within block
        if (g < limit4) {
            int pp = g >> 3, c = g & 7;        // pair-in-block, chunk-in-row
            const float* s = &srbf[pp * 33 + c * 4];
            // banks (t>>3) + 4*(t&7) + e cover 0..31: conflict-free
            float4 w = make_float4(s[0], s[1], s[2], s[3]);
            out4[base4 + g] = w;
        }
    }
}

extern "C" void kernel_launch(void* const* d_in, const int* in_sizes, int n_in,
                              void* d_out, int out_size)
{
    const float* R          = (const float*)d_in[0];
    const float* pair_mask  = (const float*)d_in[1];
    const float* point_mask = (const float*)d_in[2];
    const int*   idx_i      = (const int*)d_in[3];
    const int*   idx_j      = (const int*)d_in[4];

    const int n_pairs = in_sizes[1];
    const int n       = in_sizes[2];

    float* rbf_out = (float*)d_out;
    float* chi_out = rbf_out + (size_t)n_pairs * NRBF;

    cudaMemsetAsync(chi_out, 0, (size_t)n * 8 * sizeof(float), 0);

    int blocks = (n_pairs + 255) / 256;
    if (n <= RCAP) {
        pack_R_kernel<<<(n + 255) / 256, 256>>>(R, n);
        geo_kernel<true><<<blocks, 256>>>(R, pair_mask, point_mask, idx_i, idx_j,
                                          rbf_out, chi_out, n_pairs);
    } else {
        geo_kernel<false><<<blocks, 256>>>(R, pair_mask, point_mask, idx_i, idx_j,
                                           rbf_out, chi_out, n_pairs);
    }
}